// round 3
// baseline (speedup 1.0000x reference)
#include <cuda_runtime.h>

// ---------------- problem constants ----------------
#define T_TOK 8192          // B*S tokens
#define DIMD  2048          // model dim (K of GEMM1, N of both GEMMs)
#define EINT  1024          // expert intermediate (K of GEMM2)
#define NEXP  8
#define BM 128
#define BN 128
#define BKK 16
#define MT (T_TOK / BM)     // 64 max m-tiles per expert

// ---------------- device scratch (no allocs allowed) ----------------
__device__ int   g_perm[T_TOK];
__device__ int   g_off[NEXP + 1];
__device__ int   g_swap;                           // 1 if d_in[0] is down_proj
__device__ float g_gu[(size_t)T_TOK * 2 * EINT];   // 64 MiB: gate|up, sorted rows
__device__ float g_h [(size_t)T_TOK * EINT];       // 32 MiB: silu(g)*u, sorted rows

// ---------------- packed f32x2 helpers (Blackwell-only, PTX path) ----------------
__device__ __forceinline__ unsigned long long pk2(float lo, float hi) {
    unsigned long long r;
    asm("mov.b64 %0, {%1,%2};" : "=l"(r) : "f"(lo), "f"(hi));
    return r;
}
__device__ __forceinline__ void fma2(unsigned long long& c,
                                     unsigned long long a,
                                     unsigned long long b) {
    asm("fma.rn.f32x2 %0, %1, %2, %0;" : "+l"(c) : "l"(a), "l"(b));
}
__device__ __forceinline__ float2 unpk(unsigned long long v) {
    float2 f;
    asm("mov.b64 {%0,%1}, %2;" : "=f"(f.x), "=f"(f.y) : "l"(v));
    return f;
}

// ---------------- 0) probe: is d_in[0] x (normal ~N(0,1)) or down_proj (|v|<=0.03125)?
__global__ void probe_kernel(const float* __restrict__ p0) {
    __shared__ float smax[8];
    float m = 0.f;
    for (int i = threadIdx.x; i < 4096; i += blockDim.x)
        m = fmaxf(m, fabsf(p0[i]));
#pragma unroll
    for (int o = 16; o; o >>= 1) m = fmaxf(m, __shfl_xor_sync(0xffffffffu, m, o));
    if ((threadIdx.x & 31) == 0) smax[threadIdx.x >> 5] = m;
    __syncthreads();
    if (threadIdx.x == 0) {
        float mm = 0.f;
        for (int i = 0; i < (int)(blockDim.x >> 5); i++) mm = fmaxf(mm, smax[i]);
        g_swap = (mm < 0.1f) ? 1 : 0;   // tiny values => it's down_proj => swapped order
    }
}

// ---------------- 1) routing: counts -> offsets -> scatter perm ----------------
// expert_ids dtype is sniffed at runtime: reference says int64 but JAX silently
// downcasts to int32 (x64 disabled). If the buffer really were int64 with values
// 0..7, every odd 32-bit word is 0; genuine int32 id data fails that test with
// probability ~8^-128.
__global__ void route_kernel(const int* __restrict__ ids32) {
    __shared__ int cnt[NEXP];
    __shared__ int cur[NEXP];
    __shared__ int is64;
    int tid = threadIdx.x;
    if (tid == 0) {
        int z = 1;
        for (int i = 1; i < 256; i += 2)
            if (ids32[i] != 0) { z = 0; break; }
        is64 = z;
    }
    if (tid < NEXP) cnt[tid] = 0;
    __syncthreads();
    for (int t = tid; t < T_TOK; t += blockDim.x) {
        int e = is64 ? ids32[2 * t] : ids32[t];
        atomicAdd(&cnt[e & 7], 1);
    }
    __syncthreads();
    if (tid == 0) {
        int s = 0;
        for (int e = 0; e < NEXP; e++) { g_off[e] = s; cur[e] = s; s += cnt[e]; }
        g_off[NEXP] = s;
    }
    __syncthreads();
    for (int t = tid; t < T_TOK; t += blockDim.x) {
        int e = (is64 ? ids32[2 * t] : ids32[t]) & 7;
        int p = atomicAdd(&cur[e], 1);
        g_perm[p] = t;
    }
}

// ---------------- 2/4) grouped SGEMM ----------------
// C[m, n0..n0+127] = sum_k A[arow(m), k] * W[e][k, n0..]
// A/W each passed as a (no-swap, swap) pointer pair; g_swap selects device-side.
// GATHER_A=true : A rows via perm (GEMM1, x), C rows = sorted index (g_gu)
// GATHER_A=false: A rows contiguous (g_h), C rows scattered via perm (d_out)
template <bool GATHER_A>
__global__ __launch_bounds__(256, 2)
void gemm_kernel(const float* __restrict__ A0, const float* __restrict__ A1,
                 const float* __restrict__ W0, const float* __restrict__ W1,
                 float* __restrict__ C, int K)
{
    __shared__ float As[BKK][BM + 4];   // padded: conflict-free transposed stores
    __shared__ float Bs[BKK][BN];
    __shared__ int   pmap[BM];

    const float* __restrict__ A = g_swap ? A1 : A0;
    const float* __restrict__ W = g_swap ? W1 : W0;

    int e   = blockIdx.y / MT;
    int mt  = blockIdx.y % MT;
    int seg0 = g_off[e];
    int cnt  = g_off[e + 1] - seg0;
    if (mt * BM >= cnt) return;                 // over-provisioned tile: exit
    int row0  = seg0 + mt * BM;                 // sorted-space row base
    int valid = min(BM, cnt - mt * BM);

    int tid = threadIdx.x;
    if (tid < BM) {
        int i = (tid < valid) ? tid : 0;        // clamp for safe loads
        pmap[tid] = g_perm[row0 + i];
    }

    int n0 = blockIdx.x * BN;
    const float* Wb = W + (size_t)e * K * 2048 + n0;

    unsigned long long acc[8][4];
#pragma unroll
    for (int i = 0; i < 8; i++)
#pragma unroll
        for (int j = 0; j < 4; j++) acc[i][j] = 0ull;

    int tm = tid >> 4;      // 0..15
    int tn = tid & 15;      // 0..15

    __syncthreads();        // pmap ready

    for (int k0 = 0; k0 < K; k0 += BKK) {
        // --- load A tile: 128 rows x 16 k, 512 float4, 2 per thread, transpose ---
#pragma unroll
        for (int q = tid; q < (BM * BKK) / 4; q += 256) {
            int r  = q >> 2;                 // 0..127
            int kq = (q & 3) << 2;           // 0,4,8,12
            int src;
            if (GATHER_A) src = pmap[r];
            else          src = row0 + ((r < valid) ? r : 0);
            float4 v = *reinterpret_cast<const float4*>(&A[(size_t)src * K + k0 + kq]);
            As[kq + 0][r] = v.x; As[kq + 1][r] = v.y;
            As[kq + 2][r] = v.z; As[kq + 3][r] = v.w;
        }
        // --- load B tile: 16 k x 128 n, direct float4 ---
#pragma unroll
        for (int q = tid; q < (BKK * BN) / 4; q += 256) {
            int kr = q >> 5;                 // 0..15
            int c4 = (q & 31) << 2;          // 0..124
            float4 v = *reinterpret_cast<const float4*>(&Wb[(size_t)(k0 + kr) * 2048 + c4]);
            *reinterpret_cast<float4*>(&Bs[kr][c4]) = v;
        }
        __syncthreads();

#pragma unroll
        for (int kk = 0; kk < BKK; kk++) {
            float4 a0 = *reinterpret_cast<const float4*>(&As[kk][tm * 8]);
            float4 a1 = *reinterpret_cast<const float4*>(&As[kk][tm * 8 + 4]);
            unsigned long long b[4];
#pragma unroll
            for (int j = 0; j < 4; j++)
                b[j] = *reinterpret_cast<const unsigned long long*>(&Bs[kk][tn * 8 + 2 * j]);
            float av[8] = {a0.x, a0.y, a0.z, a0.w, a1.x, a1.y, a1.z, a1.w};
#pragma unroll
            for (int i = 0; i < 8; i++) {
                unsigned long long ap = pk2(av[i], av[i]);
#pragma unroll
                for (int j = 0; j < 4; j++) fma2(acc[i][j], ap, b[j]);
            }
        }
        __syncthreads();
    }

    // --- store 8x8 per thread ---
#pragma unroll
    for (int i = 0; i < 8; i++) {
        int m = tm * 8 + i;
        if (m < valid) {
            int crow = GATHER_A ? (row0 + m) : pmap[m];
            float o[8];
#pragma unroll
            for (int j = 0; j < 4; j++) {
                float2 f = unpk(acc[i][j]);
                o[2 * j] = f.x; o[2 * j + 1] = f.y;
            }
            float4* dst = reinterpret_cast<float4*>(&C[(size_t)crow * 2048 + n0 + tn * 8]);
            dst[0] = make_float4(o[0], o[1], o[2], o[3]);
            dst[1] = make_float4(o[4], o[5], o[6], o[7]);
        }
    }
}

// ---------------- 3) h = silu(g) * u ----------------
__global__ void act_kernel() {
    int idx = blockIdx.x * blockDim.x + threadIdx.x;           // one float4 of h
    const int total = T_TOK * EINT / 4;
    if (idx >= total) return;
    int r  = idx / (EINT / 4);
    int j4 = (idx % (EINT / 4)) * 4;
    float4 g = *reinterpret_cast<const float4*>(&g_gu[(size_t)r * 2048 + j4]);
    float4 u = *reinterpret_cast<const float4*>(&g_gu[(size_t)r * 2048 + EINT + j4]);
    float4 h;
    h.x = g.x / (1.f + __expf(-g.x)) * u.x;
    h.y = g.y / (1.f + __expf(-g.y)) * u.y;
    h.z = g.z / (1.f + __expf(-g.z)) * u.z;
    h.w = g.w / (1.f + __expf(-g.w)) * u.w;
    *reinterpret_cast<float4*>(&g_h[(size_t)r * EINT + j4]) = h;
}

// ---------------- launch ----------------
extern "C" void kernel_launch(void* const* d_in, const int* in_sizes, int n_in,
                              void* d_out, int out_size)
{
    // Nominal (dict-order) assignment; slots 0 and 3 may be swapped (both are
    // 16,777,216-element f32 tensors). probe_kernel decides; GEMMs select.
    const float* p0  = (const float*)d_in[0];   // x            OR down_proj
    const int*   ids = (const int*)d_in[1];     // int32 (JAX silently downcasts) or int64 — sniffed
    const float* gup = (const float*)d_in[2];   // gate_up_proj (fixed slot)
    const float* p3  = (const float*)d_in[3];   // down_proj    OR x
    float*       out = (float*)d_out;

    float* gu_ptr = nullptr;
    float* h_ptr  = nullptr;
    cudaGetSymbolAddress((void**)&gu_ptr, g_gu);
    cudaGetSymbolAddress((void**)&h_ptr,  g_h);

    probe_kernel<<<1, 256>>>(p0);
    route_kernel<<<1, 1024>>>(ids);
    // GEMM1: A = x (p0 normally, p3 if swapped); W = gate_up (fixed)
    gemm_kernel<true ><<<dim3(16, NEXP * MT), 256>>>(p0, p3, gup, gup, gu_ptr, DIMD);
    act_kernel<<<(T_TOK * EINT / 4 + 255) / 256, 256>>>();
    // GEMM2: A = h (fixed); W = down_proj (p3 normally, p0 if swapped)
    gemm_kernel<false><<<dim3(16, NEXP * MT), 256>>>(h_ptr, h_ptr, p3, p0, out, EINT);
}

// round 5
// speedup vs baseline: 2.4154x; 2.4154x over previous
#include <cuda_runtime.h>
#include <cuda_bf16.h>
#include <cstdint>

// ---------------- problem constants ----------------
#define T_TOK 8192
#define DIMD  2048
#define EINT  1024
#define NEXP  8
#define BM 128
#define BN 128
#define BK 32                 // bf16 k per stage
#define MT (T_TOK / BM)       // 64 max m-tiles per expert

#define ROWB 80               // smem row pitch in bytes (40 bf16) -> conflict-free ldmatrix
#define TILE_B (128 * ROWB)   // 10240 B per tile
#define STAGE_B (4 * TILE_B)  // Ahi|Alo|Bhi|Blo
#define SMEM_BYTES (512 + 2 * STAGE_B)

// ---------------- device scratch ----------------
__device__ int   g_perm[T_TOK];
__device__ int   g_off[NEXP + 1];
__device__ __nv_bfloat16 g_xhi[(size_t)T_TOK * DIMD];
__device__ __nv_bfloat16 g_xlo[(size_t)T_TOK * DIMD];
__device__ __nv_bfloat16 g_w1hi[(size_t)NEXP * 2048 * 2048];  // transposed [e][n][k]
__device__ __nv_bfloat16 g_w1lo[(size_t)NEXP * 2048 * 2048];
__device__ __nv_bfloat16 g_w2hi[(size_t)NEXP * 2048 * 1024];  // transposed [e][n][k]
__device__ __nv_bfloat16 g_w2lo[(size_t)NEXP * 2048 * 1024];
__device__ float g_gu[(size_t)T_TOK * 2048];                  // GEMM1 out (sorted rows)
__device__ __nv_bfloat16 g_hhi[(size_t)T_TOK * EINT];
__device__ __nv_bfloat16 g_hlo[(size_t)T_TOK * EINT];

// ---------------- PTX helpers (generic compute_103-safe) ----------------
__device__ __forceinline__ uint32_t smem_u32(const void* p) {
    uint32_t a;
    asm("{ .reg .u64 t; cvta.to.shared.u64 t, %1; cvt.u32.u64 %0, t; }" : "=r"(a) : "l"(p));
    return a;
}
#define CP16(s, g)  asm volatile("cp.async.cg.shared.global [%0], [%1], 16;" :: "r"(s), "l"(g))
#define CP_COMMIT() asm volatile("cp.async.commit_group;" ::: "memory")
#define CP_WAIT1()  asm volatile("cp.async.wait_group 1;" ::: "memory")
#define CP_WAIT0()  asm volatile("cp.async.wait_group 0;" ::: "memory")

__device__ __forceinline__ void ldsm4(uint32_t* r, uint32_t a) {
    asm volatile("ldmatrix.sync.aligned.m8n8.x4.shared.b16 {%0,%1,%2,%3}, [%4];"
                 : "=r"(r[0]), "=r"(r[1]), "=r"(r[2]), "=r"(r[3]) : "r"(a));
}
__device__ __forceinline__ void mma16816(float* d, const uint32_t* a, const uint32_t* b) {
    asm volatile(
        "mma.sync.aligned.m16n8k16.row.col.f32.bf16.bf16.f32 "
        "{%0,%1,%2,%3}, {%4,%5,%6,%7}, {%8,%9}, {%0,%1,%2,%3};"
        : "+f"(d[0]), "+f"(d[1]), "+f"(d[2]), "+f"(d[3])
        : "r"(a[0]), "r"(a[1]), "r"(a[2]), "r"(a[3]), "r"(b[0]), "r"(b[1]));
}
__device__ __forceinline__ void split_bf16(float v, __nv_bfloat16& h, __nv_bfloat16& l) {
    h = __float2bfloat16(v);
    l = __float2bfloat16(v - __bfloat162float(h));
}

// ---------------- 1) routing (int32 ids; int64 sniff kept) ----------------
__global__ void route_kernel(const int* __restrict__ ids32) {
    __shared__ int cnt[NEXP];
    __shared__ int cur[NEXP];
    __shared__ int is64;
    int tid = threadIdx.x;
    if (tid == 0) {
        int z = 1;
        for (int i = 1; i < 256; i += 2)
            if (ids32[i] != 0) { z = 0; break; }
        is64 = z;
    }
    if (tid < NEXP) cnt[tid] = 0;
    __syncthreads();
    for (int t = tid; t < T_TOK; t += blockDim.x)
        atomicAdd(&cnt[(is64 ? ids32[2 * t] : ids32[t]) & 7], 1);
    __syncthreads();
    if (tid == 0) {
        int s = 0;
        for (int e = 0; e < NEXP; e++) { g_off[e] = s; cur[e] = s; s += cnt[e]; }
        g_off[NEXP] = s;
    }
    __syncthreads();
    for (int t = tid; t < T_TOK; t += blockDim.x) {
        int e = (is64 ? ids32[2 * t] : ids32[t]) & 7;
        g_perm[atomicAdd(&cur[e], 1)] = t;
    }
}

// ---------------- 2) split x -> bf16 hi/lo ----------------
__global__ void split_x_kernel(const float* __restrict__ x) {
    int i = blockIdx.x * blockDim.x + threadIdx.x;
    const int total4 = T_TOK * DIMD / 4;
    if (i >= total4) return;
    float4 v = reinterpret_cast<const float4*>(x)[i];
    __nv_bfloat16 h[4], l[4];
    split_bf16(v.x, h[0], l[0]); split_bf16(v.y, h[1], l[1]);
    split_bf16(v.z, h[2], l[2]); split_bf16(v.w, h[3], l[3]);
    reinterpret_cast<uint2*>(g_xhi)[i] = *reinterpret_cast<uint2*>(h);
    reinterpret_cast<uint2*>(g_xlo)[i] = *reinterpret_cast<uint2*>(l);
}

// ---------------- 3) transpose + split weights: W[e][k][n] -> Wt[e][n][k] ----
__global__ void wsplit_kernel(const float* __restrict__ W,
                              __nv_bfloat16* __restrict__ Hi,
                              __nv_bfloat16* __restrict__ Lo, int K) {
    __shared__ float t[32][33];
    const int N = 2048;
    int e = blockIdx.z;
    const float* We = W + (size_t)e * K * N;
    __nv_bfloat16* He = Hi + (size_t)e * N * K;
    __nv_bfloat16* Le = Lo + (size_t)e * N * K;
    int n0 = blockIdx.x * 32, k0 = blockIdx.y * 32;
    int tx = threadIdx.x, ty = threadIdx.y;     // 32 x 8
#pragma unroll
    for (int j = 0; j < 4; j++) {
        int k = k0 + ty + j * 8;
        t[ty + j * 8][tx] = We[(size_t)k * N + n0 + tx];
    }
    __syncthreads();
#pragma unroll
    for (int j = 0; j < 4; j++) {
        int n = n0 + ty + j * 8;
        float v = t[tx][ty + j * 8];
        __nv_bfloat16 h, l;
        split_bf16(v, h, l);
        He[(size_t)n * K + k0 + tx] = h;
        Le[(size_t)n * K + k0 + tx] = l;
    }
}

// ---------------- 4/6) grouped bf16x3 mma.sync GEMM ----------------
// D[m, n0:n0+128] = sum_k A[row(m), k] * Wt[e][n, k]  (fp32 accum)
// GATHER_A=true : A rows via perm (x), C rows sorted (g_gu)
// GATHER_A=false: A rows contiguous (h), C rows scattered via perm (d_out)
template <bool GATHER_A>
__global__ void __launch_bounds__(256)
gemm_mma(const __nv_bfloat16* __restrict__ Ahi, const __nv_bfloat16* __restrict__ Alo,
         const __nv_bfloat16* __restrict__ Whi, const __nv_bfloat16* __restrict__ Wlo,
         float* __restrict__ C, int K)
{
    extern __shared__ char smem[];
    int* pmap = reinterpret_cast<int*>(smem);
    uint32_t sb = smem_u32(smem);
    uint32_t tiles = sb + 512;

    int e  = blockIdx.y / MT;
    int mt = blockIdx.y % MT;
    int seg0 = g_off[e];
    int cnt  = g_off[e + 1] - seg0;
    if (mt * BM >= cnt) return;
    int row0  = seg0 + mt * BM;
    int valid = min(BM, cnt - mt * BM);

    int tid = threadIdx.x, wid = tid >> 5, l = tid & 31;
    if (tid < BM) pmap[tid] = g_perm[row0 + ((tid < valid) ? tid : 0)];
    __syncthreads();

    int n0 = blockIdx.x * BN;
    size_t wbase = ((size_t)e * 2048 + n0) * (size_t)K;

    // cp.async per-thread assignments: rows r1 (0..63) and r2 (64..127), chunk c (0..3)
    int r1 = tid >> 2, c = tid & 3;
    int r2 = r1 + 64;
    size_t arow1, arow2;
    if (GATHER_A) { arow1 = (size_t)pmap[r1]; arow2 = (size_t)pmap[r2]; }
    else {
        arow1 = (size_t)(row0 + ((r1 < valid) ? r1 : 0));
        arow2 = (size_t)(row0 + ((r2 < valid) ? r2 : 0));
    }
    uint32_t so1 = (uint32_t)(r1 * ROWB + c * 16);
    uint32_t so2 = (uint32_t)(r2 * ROWB + c * 16);

    int bm = (wid & 1) * 64;      // warp m-offset
    int bn = (wid >> 1) * 32;     // warp n-offset

    float acc[4][4][4];
#pragma unroll
    for (int i = 0; i < 4; i++)
#pragma unroll
        for (int j = 0; j < 4; j++)
#pragma unroll
            for (int q = 0; q < 4; q++) acc[i][j][q] = 0.f;

    auto load_stage = [&](int st, int k0) {
        uint32_t s = tiles + st * STAGE_B;
        size_t ka = (size_t)k0 + c * 8;
        size_t ga1 = arow1 * K + ka, ga2 = arow2 * K + ka;
        size_t gb1 = wbase + (size_t)r1 * K + ka, gb2 = wbase + (size_t)r2 * K + ka;
        CP16(s + so1,              Ahi + ga1);
        CP16(s + TILE_B + so1,     Alo + ga1);
        CP16(s + 2 * TILE_B + so1, Whi + gb1);
        CP16(s + 3 * TILE_B + so1, Wlo + gb1);
        CP16(s + so2,              Ahi + ga2);
        CP16(s + TILE_B + so2,     Alo + ga2);
        CP16(s + 2 * TILE_B + so2, Whi + gb2);
        CP16(s + 3 * TILE_B + so2, Wlo + gb2);
    };

    auto compute = [&](int st) {
        uint32_t sA  = tiles + st * STAGE_B;
        uint32_t sAl = sA + TILE_B, sB = sA + 2 * TILE_B, sBl = sA + 3 * TILE_B;
#pragma unroll
        for (int ks = 0; ks < 2; ks++) {
            // B fragments: pair p covers ntiles 2p, 2p+1
            uint32_t bh[8], bl[8];
#pragma unroll
            for (int p = 0; p < 2; p++) {
                uint32_t row = bn + p * 16 + ((l >> 4) << 3) + (l & 7);
                uint32_t kb  = ks * 32 + ((l >> 3) & 1) * 16;
                uint32_t off = row * ROWB + kb;
                ldsm4(&bh[p * 4], sB + off);
                ldsm4(&bl[p * 4], sBl + off);
            }
#pragma unroll
            for (int mtile = 0; mtile < 4; mtile++) {
                uint32_t row = bm + mtile * 16 + (l & 15);
                uint32_t kb  = ks * 32 + (l >> 4) * 16;
                uint32_t off = row * ROWB + kb;
                uint32_t ah[4], al4[4];
                ldsm4(ah, sA + off);
                ldsm4(al4, sAl + off);
#pragma unroll
                for (int nt = 0; nt < 4; nt++) {
                    mma16816(acc[mtile][nt], ah,  &bh[nt * 2]);
                    mma16816(acc[mtile][nt], ah,  &bl[nt * 2]);
                    mma16816(acc[mtile][nt], al4, &bh[nt * 2]);
                }
            }
        }
    };

    const int KI = K / BK;
    load_stage(0, 0);
    CP_COMMIT();
    for (int it = 0; it < KI; it++) {
        int b = it & 1;
        if (it + 1 < KI) { load_stage(b ^ 1, (it + 1) * BK); CP_COMMIT(); CP_WAIT1(); }
        else             { CP_WAIT0(); }
        __syncthreads();
        compute(b);
        __syncthreads();
    }

    // ---------------- epilogue ----------------
#pragma unroll
    for (int mtile = 0; mtile < 4; mtile++) {
        int mbase = bm + mtile * 16 + (l >> 2);
#pragma unroll
        for (int half = 0; half < 2; half++) {
            int m = mbase + half * 8;
            if (m < valid) {
                int crow = GATHER_A ? (row0 + m) : pmap[m];
                float* dst = C + (size_t)crow * 2048 + n0 + bn + 2 * (l & 3);
#pragma unroll
                for (int nt = 0; nt < 4; nt++) {
                    *reinterpret_cast<float2*>(dst + nt * 8) =
                        make_float2(acc[mtile][nt][half * 2], acc[mtile][nt][half * 2 + 1]);
                }
            }
        }
    }
}

// ---------------- 5) act: h = silu(g)*u, split to bf16 hi/lo ----------------
__global__ void act_split_kernel() {
    int i = blockIdx.x * blockDim.x + threadIdx.x;
    const int total4 = T_TOK * EINT / 4;
    if (i >= total4) return;
    int r = i / (EINT / 4), j4 = (i % (EINT / 4)) * 4;
    float4 g = *reinterpret_cast<const float4*>(&g_gu[(size_t)r * 2048 + j4]);
    float4 u = *reinterpret_cast<const float4*>(&g_gu[(size_t)r * 2048 + EINT + j4]);
    float h0 = g.x / (1.f + __expf(-g.x)) * u.x;
    float h1 = g.y / (1.f + __expf(-g.y)) * u.y;
    float h2 = g.z / (1.f + __expf(-g.z)) * u.z;
    float h3 = g.w / (1.f + __expf(-g.w)) * u.w;
    __nv_bfloat16 hh[4], ll[4];
    split_bf16(h0, hh[0], ll[0]); split_bf16(h1, hh[1], ll[1]);
    split_bf16(h2, hh[2], ll[2]); split_bf16(h3, hh[3], ll[3]);
    reinterpret_cast<uint2*>(g_hhi)[i] = *reinterpret_cast<uint2*>(hh);
    reinterpret_cast<uint2*>(g_hlo)[i] = *reinterpret_cast<uint2*>(ll);
}

// ---------------- launch ----------------
extern "C" void kernel_launch(void* const* d_in, const int* in_sizes, int n_in,
                              void* d_out, int out_size)
{
    const float* x   = (const float*)d_in[0];
    const int*   ids = (const int*)d_in[1];
    const float* gup = (const float*)d_in[2];   // [8,2048,2048]
    const float* dwn = (const float*)d_in[3];   // [8,1024,2048]
    float*       out = (float*)d_out;

    __nv_bfloat16 *xhi, *xlo, *w1hi, *w1lo, *w2hi, *w2lo, *hhi, *hlo;
    float* gu;
    cudaGetSymbolAddress((void**)&xhi, g_xhi);
    cudaGetSymbolAddress((void**)&xlo, g_xlo);
    cudaGetSymbolAddress((void**)&w1hi, g_w1hi);
    cudaGetSymbolAddress((void**)&w1lo, g_w1lo);
    cudaGetSymbolAddress((void**)&w2hi, g_w2hi);
    cudaGetSymbolAddress((void**)&w2lo, g_w2lo);
    cudaGetSymbolAddress((void**)&hhi, g_hhi);
    cudaGetSymbolAddress((void**)&hlo, g_hlo);
    cudaGetSymbolAddress((void**)&gu, g_gu);

    cudaFuncSetAttribute(gemm_mma<true>,  cudaFuncAttributeMaxDynamicSharedMemorySize, SMEM_BYTES);
    cudaFuncSetAttribute(gemm_mma<false>, cudaFuncAttributeMaxDynamicSharedMemorySize, SMEM_BYTES);

    route_kernel<<<1, 1024>>>(ids);
    split_x_kernel<<<(T_TOK * DIMD / 4 + 255) / 256, 256>>>(x);
    wsplit_kernel<<<dim3(64, 64, NEXP), dim3(32, 8)>>>(gup, w1hi, w1lo, 2048);
    wsplit_kernel<<<dim3(64, 32, NEXP), dim3(32, 8)>>>(dwn, w2hi, w2lo, 1024);

    gemm_mma<true ><<<dim3(16, NEXP * MT), 256, SMEM_BYTES>>>(xhi, xlo, w1hi, w1lo, gu, DIMD);
    act_split_kernel<<<(T_TOK * EINT / 4 + 255) / 256, 256>>>();
    gemm_mma<false><<<dim3(16, NEXP * MT), 256, SMEM_BYTES>>>(hhi, hlo, w2hi, w2lo, out, EINT);
}